// round 15
// baseline (speedup 1.0000x reference)
#include <cuda_runtime.h>
#include <cstdint>

#define N_TOKENS  8192
#define IN_DIM    1024
#define EXP_DIM   4096
#define N_EXPERTS 8

// Scratch (device globals: no allocation allowed anywhere in this file)
__device__ float g_H[(size_t)(N_EXPERTS + 1) * N_TOKENS * EXP_DIM]; // z=0 gate hidden, z=1..8 experts
__device__ float g_P[(size_t)N_EXPERTS * N_TOKENS * IN_DIM];        // per-expert partials
__device__ float g_gate[N_TOKENS * N_EXPERTS];
__device__ float g_xr[(size_t)N_TOKENS * IN_DIM];
__device__ float g_Wg1r[(size_t)IN_DIM * EXP_DIM];
__device__ float g_W1r[(size_t)N_EXPERTS * IN_DIM * EXP_DIM];
__device__ float g_W2r[(size_t)N_EXPERTS * EXP_DIM * IN_DIM];

// ---------------- Tile geometry ----------------
// Block tile 128x256x32, 256 threads = 8 warps in 2(M) x 4(N), warp tile 64x64.
static constexpr int BM = 128, BN = 256, BK = 32;
static constexpr int A_STRIDE = 36;    // words/row (ldmatrix phase-conflict-free)
static constexpr int B_STRIDE = 264;   // words/row: 256+8 pad (frag banks conflict-free)
static constexpr int A_WORDS = BM * A_STRIDE;        // 4608
static constexpr int B_WORDS = BK * B_STRIDE;        // 8448
static constexpr int BUF_WORDS = A_WORDS + B_WORDS;  // 13056 words = 52224 B
static constexpr int N_STAGES = 4;
static constexpr int SMEM_BYTES = N_STAGES * BUF_WORDS * 4;  // 208896 B

// ---------------- PTX helpers (sm_75/80-baseline only) ----------------
__device__ __forceinline__ void cp16(uint32_t saddr, const void* gptr) {
    asm volatile("cp.async.cg.shared.global [%0], [%1], 16;"
                 :: "r"(saddr), "l"(gptr));
}
__device__ __forceinline__ void cp_commit() {
    asm volatile("cp.async.commit_group;" ::: "memory");
}
template<int N> __device__ __forceinline__ void cp_wait() {
    asm volatile("cp.async.wait_group %0;" :: "n"(N) : "memory");
}
__device__ __forceinline__ uint32_t smem_u32(const void* p) {
    uint32_t a;
    asm("{ .reg .u64 t; cvta.to.shared.u64 t, %1; cvt.u32.u64 %0, t; }"
        : "=r"(a) : "l"(p));
    return a;
}
// tf32 m16k8 A fragment in one instruction (lane l: row l&15, word-group (l>>4)*4)
__device__ __forceinline__ void ldsm_x4(uint32_t* d, uint32_t saddr) {
    asm volatile("ldmatrix.sync.aligned.m8n8.x4.shared.b16 {%0,%1,%2,%3}, [%4];"
                 : "=r"(d[0]), "=r"(d[1]), "=r"(d[2]), "=r"(d[3])
                 : "r"(saddr));
}
__device__ __forceinline__ uint32_t f2tf(float x) {
    uint32_t r;
    asm("cvt.rna.tf32.f32 %0, %1;" : "=r"(r) : "f"(x));
    return r;
}
__device__ __forceinline__ void mma_tf32(float* c, const uint32_t* a, const uint32_t* b) {
    asm volatile(
        "mma.sync.aligned.m16n8k8.row.col.f32.tf32.tf32.f32 "
        "{%0,%1,%2,%3}, {%4,%5,%6,%7}, {%8,%9}, {%0,%1,%2,%3};"
        : "+f"(c[0]), "+f"(c[1]), "+f"(c[2]), "+f"(c[3])
        : "r"(a[0]), "r"(a[1]), "r"(a[2]), "r"(a[3]),
          "r"(b[0]), "r"(b[1]));
}

// ---------------------------------------------------------------------------
// tf32 pre-round passes
// ---------------------------------------------------------------------------
__device__ __forceinline__ float4 rnd4(float4 v) {
    v.x = __uint_as_float(f2tf(v.x));
    v.y = __uint_as_float(f2tf(v.y));
    v.z = __uint_as_float(f2tf(v.z));
    v.w = __uint_as_float(f2tf(v.w));
    return v;
}
__global__ void __launch_bounds__(256)
round_tf32_kernel(const float4* __restrict__ in, float4* __restrict__ out, int n4)
{
    const int i = blockIdx.x * blockDim.x + threadIdx.x;
    if (i < n4) out[i] = rnd4(in[i]);
}
__global__ void __launch_bounds__(256)
round2_tf32_kernel(const float4* __restrict__ a, float4* __restrict__ ao, int na4,
                   const float4* __restrict__ b, float4* __restrict__ bo, int nb4)
{
    const int i = blockIdx.x * blockDim.x + threadIdx.x;
    if (i < na4) ao[i] = rnd4(a[i]);
    else if (i < na4 + nb4) bo[i - na4] = rnd4(b[i - na4]);
}

// ---------------------------------------------------------------------------
// Fused batched tf32 GEMM, 4-stage cp.async, ldmatrix A frags, CVT-free,
// register-double-buffered fragments (software-pipelined across ks).
// MODE 0 (up):  z=0: H0 = rna(relu(xr@Wg1r+bg1)); z>=1: Hz = rna(relu(xr@W1r[z-1]+b1[z-1]))
// MODE 1 (down): P[z] = gate[:,z] * (H[z+1] @ W2r[z] + b2[z])
// ---------------------------------------------------------------------------
template<int MODE>
__global__ void __launch_bounds__(256, 1)
moe_fused(const float* __restrict__ Abase,
          const float* __restrict__ B0,
          const float* __restrict__ B1,
          const float* __restrict__ bias0,
          const float* __restrict__ bias1,
          const float* __restrict__ gate,
          float* __restrict__ Cbase)
{
    const int K = MODE ? EXP_DIM : IN_DIM;
    const int N = MODE ? IN_DIM : EXP_DIM;
    const int z = blockIdx.z;

    const float *A, *B, *bias;
    float* C;
    if (MODE == 0) {
        A    = Abase;
        B    = z ? B1 + (size_t)(z - 1) * IN_DIM * EXP_DIM : B0;
        bias = z ? bias1 + (size_t)(z - 1) * EXP_DIM : bias0;
        C    = Cbase + (size_t)z * N_TOKENS * EXP_DIM;
    } else {
        A    = Abase + (size_t)(z + 1) * N_TOKENS * EXP_DIM;
        B    = B0 + (size_t)z * EXP_DIM * IN_DIM;
        bias = bias0 + (size_t)z * IN_DIM;
        C    = Cbase + (size_t)z * N_TOKENS * IN_DIM;
    }

    extern __shared__ __align__(16) float smem[];
    const int tid    = threadIdx.x;
    const int lane   = tid & 31;
    const int wid    = tid >> 5;
    const int warp_m = wid >> 2;       // 0..1
    const int warp_n = wid & 3;        // 0..3
    const int wm0    = warp_m * 64;
    const int wn0    = warp_n * 64;
    const int m0     = blockIdx.y * BM;
    const int n0     = blockIdx.x * BN;
    const int r      = lane >> 2;      // 0..7
    const int q      = lane & 3;       // 0..3

    float acc[4][8][4];
    #pragma unroll
    for (int mi = 0; mi < 4; mi++)
        #pragma unroll
        for (int ni = 0; ni < 8; ni++)
            #pragma unroll
            for (int j = 0; j < 4; j++) acc[mi][ni][j] = 0.f;

    const uint32_t s_base = smem_u32(smem);
    const int KT = K >> 5;

    const int a_id_row = tid >> 3, a_id_kq = tid & 7;
    const int b_id_row = tid >> 6, b_id_nq = tid & 63;

    auto load_tile = [&](int kt, int buf) {
        const int k0 = kt << 5;
        const uint32_t abase = s_base + (uint32_t)buf * BUF_WORDS * 4u;
        const uint32_t bbase = abase + (uint32_t)A_WORDS * 4u;
        #pragma unroll
        for (int i = 0; i < 4; i++) {
            const int row = a_id_row + (i << 5);
            cp16(abase + (uint32_t)(row * A_STRIDE + (a_id_kq << 2)) * 4u,
                 A + (size_t)(m0 + row) * K + k0 + (a_id_kq << 2));
        }
        #pragma unroll
        for (int i = 0; i < 8; i++) {
            const int row = b_id_row + (i << 2);
            cp16(bbase + (uint32_t)(row * B_STRIDE + (b_id_nq << 2)) * 4u,
                 B + (size_t)(k0 + row) * N + n0 + (b_id_nq << 2));
        }
    };

    load_tile(0, 0);
    cp_commit();
    if (KT > 1) { load_tile(1, 1); cp_commit(); }
    if (KT > 2) { load_tile(2, 2); cp_commit(); }

    // ldmatrix per-lane source offset (row l&15, word-group (l>>4)*4)
    const uint32_t a_frag_off =
        (uint32_t)(((wm0 + (lane & 15)) * A_STRIDE + ((lane >> 4) << 2)) << 2);

    int cur = 0, pre = 3;

    for (int kt = 0; kt < KT; kt++) {
        if (kt < KT - 2)      cp_wait<2>();
        else if (kt == KT - 2) cp_wait<1>();
        else                   cp_wait<0>();
        __syncthreads();

        if (kt + 3 < KT) { load_tile(kt + 3, pre); cp_commit(); }

        const uint32_t a_frag = s_base + (uint32_t)cur * BUF_WORDS * 4u + a_frag_off;
        const uint32_t* __restrict__ Bq =
            reinterpret_cast<const uint32_t*>(smem + (size_t)cur * BUF_WORDS)
            + A_WORDS + q * B_STRIDE + wn0 + r;

        // Register-double-buffered fragments: load ks+1 while issuing ks's MMAs.
        uint32_t af[2][4][4];
        uint32_t bf[2][8][2];
        #pragma unroll
        for (int mi = 0; mi < 4; mi++)
            ldsm_x4(af[0][mi], a_frag + (uint32_t)(((mi << 4) * A_STRIDE) << 2));
        #pragma unroll
        for (int ni = 0; ni < 8; ni++) {
            bf[0][ni][0] = Bq[ni << 3];
            bf[0][ni][1] = Bq[4 * B_STRIDE + (ni << 3)];
        }

        #pragma unroll
        for (int ks = 0; ks < 4; ks++) {
            const int cb = ks & 1, nb = cb ^ 1;
            if (ks < 3) {
                const int kb2 = (ks + 1) << 3;
                #pragma unroll
                for (int mi = 0; mi < 4; mi++)
                    ldsm_x4(af[nb][mi],
                            a_frag + (uint32_t)((((mi << 4) * A_STRIDE) + kb2) << 2));
                const uint32_t* __restrict__ p = Bq + kb2 * B_STRIDE;
                #pragma unroll
                for (int ni = 0; ni < 8; ni++) {
                    bf[nb][ni][0] = p[ni << 3];
                    bf[nb][ni][1] = p[4 * B_STRIDE + (ni << 3)];
                }
            }
            #pragma unroll
            for (int mi = 0; mi < 4; mi++)
                #pragma unroll
                for (int ni = 0; ni < 8; ni++)
                    mma_tf32(acc[mi][ni], af[cb][mi], bf[cb][ni]);
        }

        cur = (cur + 1) & (N_STAGES - 1);
        pre = (pre + 1) & (N_STAGES - 1);
    }

    // ---------------- Epilogue ----------------
    float gwv[4][2];
    if (MODE == 1) {
        #pragma unroll
        for (int mi = 0; mi < 4; mi++)
            #pragma unroll
            for (int h = 0; h < 2; h++) {
                const int m = m0 + wm0 + (mi << 4) + r + (h << 3);
                gwv[mi][h] = __ldg(gate + (size_t)m * N_EXPERTS + z);
            }
    }

    #pragma unroll
    for (int ni = 0; ni < 8; ni++) {
        const int n = n0 + wn0 + (ni << 3) + (q << 1);
        const float b0 = __ldg(bias + n);
        const float b1v = __ldg(bias + n + 1);
        #pragma unroll
        for (int mi = 0; mi < 4; mi++) {
            #pragma unroll
            for (int h = 0; h < 2; h++) {
                const int m = m0 + wm0 + (mi << 4) + r + (h << 3);
                float v0 = acc[mi][ni][2 * h]     + b0;
                float v1 = acc[mi][ni][2 * h + 1] + b1v;
                float2* p = reinterpret_cast<float2*>(C + (size_t)m * N + n);
                if (MODE == 0) {
                    v0 = __uint_as_float(f2tf(fmaxf(v0, 0.f)));
                    v1 = __uint_as_float(f2tf(fmaxf(v1, 0.f)));
                } else {
                    v0 *= gwv[mi][h];
                    v1 *= gwv[mi][h];
                }
                *p = make_float2(v0, v1);
            }
        }
    }
}

// ---------------------------------------------------------------------------
// out = sum_e P[e]  (float4, deterministic fp32 order)
// ---------------------------------------------------------------------------
__global__ void __launch_bounds__(256)
reduce8_kernel(const float4* __restrict__ P, float4* __restrict__ out, int n4)
{
    const int i = blockIdx.x * blockDim.x + threadIdx.x;
    if (i < n4) {
        float4 s = P[i];
        #pragma unroll
        for (int e = 1; e < N_EXPERTS; e++) {
            const float4 t = P[(size_t)e * n4 + i];
            s.x += t.x; s.y += t.y; s.z += t.z; s.w += t.w;
        }
        out[i] = s;
    }
}

// ---------------------------------------------------------------------------
// Gate logits + softmax: one warp per token.
// ---------------------------------------------------------------------------
__global__ void __launch_bounds__(256)
gate_softmax_kernel(const float* __restrict__ G,
                    const float* __restrict__ Wg2,
                    const float* __restrict__ bg2,
                    float* __restrict__ gate)
{
    const int token = (blockIdx.x * blockDim.x + threadIdx.x) >> 5;
    const int lane = threadIdx.x & 31;
    const float* g = G + (size_t)token * EXP_DIM;

    float acc[8];
    #pragma unroll
    for (int e = 0; e < 8; e++) acc[e] = 0.f;

    for (int h = lane; h < EXP_DIM; h += 32) {
        const float gv = g[h];
        const float4* w = reinterpret_cast<const float4*>(Wg2 + (size_t)h * 8);
        const float4 wa = w[0];
        const float4 wb = w[1];
        acc[0] = fmaf(gv, wa.x, acc[0]);
        acc[1] = fmaf(gv, wa.y, acc[1]);
        acc[2] = fmaf(gv, wa.z, acc[2]);
        acc[3] = fmaf(gv, wa.w, acc[3]);
        acc[4] = fmaf(gv, wb.x, acc[4]);
        acc[5] = fmaf(gv, wb.y, acc[5]);
        acc[6] = fmaf(gv, wb.z, acc[6]);
        acc[7] = fmaf(gv, wb.w, acc[7]);
    }
    #pragma unroll
    for (int o = 16; o > 0; o >>= 1) {
        #pragma unroll
        for (int e = 0; e < 8; e++)
            acc[e] += __shfl_xor_sync(0xffffffff, acc[e], o);
    }
    if (lane == 0) {
        float l[8], p[8];
        float m = -1e30f;
        #pragma unroll
        for (int e = 0; e < 8; e++) { l[e] = acc[e] + bg2[e]; m = fmaxf(m, l[e]); }
        float s = 0.f;
        #pragma unroll
        for (int e = 0; e < 8; e++) { p[e] = expf(l[e] - m); s += p[e]; }
        const float inv = 1.f / s;
        #pragma unroll
        for (int e = 0; e < 8; e++) gate[(size_t)token * 8 + e] = p[e] * inv;
    }
}

// ---------------------------------------------------------------------------
// 7 launches: round2(x,Wg1) -> round(W1) -> round(W2) -> fused up (z=0..8)
// -> softmax -> fused down (z=0..7, partials) -> reduce.
// ---------------------------------------------------------------------------
extern "C" void kernel_launch(void* const* d_in, const int* in_sizes, int n_in,
                              void* d_out, int out_size) {
    (void)in_sizes; (void)n_in; (void)out_size;
    const float* x   = (const float*)d_in[0];
    const float* Wg1 = (const float*)d_in[1];
    const float* bg1 = (const float*)d_in[2];
    const float* Wg2 = (const float*)d_in[3];
    const float* bg2 = (const float*)d_in[4];
    const float* W1  = (const float*)d_in[5];
    const float* b1  = (const float*)d_in[6];
    const float* W2  = (const float*)d_in[7];
    const float* b2  = (const float*)d_in[8];
    float* out = (float*)d_out;

    float *H, *P, *gate, *xr, *Wg1r, *W1r, *W2r;
    cudaGetSymbolAddress((void**)&H,    g_H);
    cudaGetSymbolAddress((void**)&P,    g_P);
    cudaGetSymbolAddress((void**)&gate, g_gate);
    cudaGetSymbolAddress((void**)&xr,   g_xr);
    cudaGetSymbolAddress((void**)&Wg1r, g_Wg1r);
    cudaGetSymbolAddress((void**)&W1r,  g_W1r);
    cudaGetSymbolAddress((void**)&W2r,  g_W2r);

    cudaFuncSetAttribute(moe_fused<0>, cudaFuncAttributeMaxDynamicSharedMemorySize,
                         SMEM_BYTES);
    cudaFuncSetAttribute(moe_fused<1>, cudaFuncAttributeMaxDynamicSharedMemorySize,
                         SMEM_BYTES);

    // 1: round x + Wg1
    {
        const int na4 = (N_TOKENS * IN_DIM) / 4;
        const int nb4 = (IN_DIM * EXP_DIM) / 4;
        round2_tf32_kernel<<<(na4 + nb4 + 255) / 256, 256>>>(
            (const float4*)x, (float4*)xr, na4,
            (const float4*)Wg1, (float4*)Wg1r, nb4);
    }
    // 2: round W1, 3: round W2
    {
        const int n4 = (int)(((size_t)N_EXPERTS * IN_DIM * EXP_DIM) >> 2);
        round_tf32_kernel<<<(n4 + 255) / 256, 256>>>(
            (const float4*)W1, (float4*)W1r, n4);
        round_tf32_kernel<<<(n4 + 255) / 256, 256>>>(
            (const float4*)W2, (float4*)W2r, n4);
    }

    // 4: fused up-GEMMs (gate hidden + 8 experts)
    moe_fused<0><<<dim3(EXP_DIM / BN, N_TOKENS / BM, N_EXPERTS + 1), 256, SMEM_BYTES>>>(
        xr, Wg1r, W1r, bg1, b1, nullptr, H);

    // 5: gate softmax (reads H z=0)
    gate_softmax_kernel<<<N_TOKENS / 8, 256>>>(H, Wg2, bg2, gate);

    // 6: fused down-GEMMs -> per-expert partials
    moe_fused<1><<<dim3(IN_DIM / BN, N_TOKENS / BM, N_EXPERTS), 256, SMEM_BYTES>>>(
        H, W2r, nullptr, b2, nullptr, gate, P);

    // 7: reduce partials -> out
    {
        const int n4 = (N_TOKENS * IN_DIM) / 4;
        reduce8_kernel<<<(n4 + 255) / 256, 256>>>((const float4*)P, (float4*)out, n4);
    }
}

// round 16
// speedup vs baseline: 1.0737x; 1.0737x over previous
#include <cuda_runtime.h>
#include <cstdint>

#define N_TOKENS  8192
#define IN_DIM    1024
#define EXP_DIM   4096
#define N_EXPERTS 8

// Scratch (device globals: no allocation allowed anywhere in this file)
__device__ float g_H[(size_t)(N_EXPERTS + 1) * N_TOKENS * EXP_DIM]; // z=0 gate hidden, z=1..8 experts
__device__ float g_P[(size_t)N_EXPERTS * N_TOKENS * IN_DIM];        // per-expert partials
__device__ float g_gate[N_TOKENS * N_EXPERTS];
__device__ float g_xr[(size_t)N_TOKENS * IN_DIM];
__device__ float g_Wg1r[(size_t)IN_DIM * EXP_DIM];
__device__ float g_W1r[(size_t)N_EXPERTS * IN_DIM * EXP_DIM];
__device__ float g_W2r[(size_t)N_EXPERTS * EXP_DIM * IN_DIM];

// ---------------- Tile geometry ----------------
// Block tile 128x128x32, 128 threads = 4 warps in 2(M) x 2(N), warp tile 64x64.
// ~210 regs/thread, 107.5 KB smem/CTA -> 2 CTAs/SM: cross-CTA overlap hides
// the per-CTA barrier + frag-load bursts that capped tensor at 62.5%.
static constexpr int BM = 128, BN = 128, BK = 32;
static constexpr int A_STRIDE = 36;    // words/row (ldmatrix phase-conflict-free)
static constexpr int B_STRIDE = 136;   // words/row: 128+8 pad (frag banks 8q+8ni+r, conflict-free)
static constexpr int A_WORDS = BM * A_STRIDE;        // 4608
static constexpr int B_WORDS = BK * B_STRIDE;        // 4352
static constexpr int BUF_WORDS = A_WORDS + B_WORDS;  // 8960 words = 35840 B
static constexpr int N_STAGES = 3;
static constexpr int SMEM_BYTES = N_STAGES * BUF_WORDS * 4;  // 107520 B

// ---------------- PTX helpers (sm_75/80-baseline only) ----------------
__device__ __forceinline__ void cp16(uint32_t saddr, const void* gptr) {
    asm volatile("cp.async.cg.shared.global [%0], [%1], 16;"
                 :: "r"(saddr), "l"(gptr));
}
__device__ __forceinline__ void cp_commit() {
    asm volatile("cp.async.commit_group;" ::: "memory");
}
template<int N> __device__ __forceinline__ void cp_wait() {
    asm volatile("cp.async.wait_group %0;" :: "n"(N) : "memory");
}
__device__ __forceinline__ uint32_t smem_u32(const void* p) {
    uint32_t a;
    asm("{ .reg .u64 t; cvta.to.shared.u64 t, %1; cvt.u32.u64 %0, t; }"
        : "=r"(a) : "l"(p));
    return a;
}
// tf32 m16k8 A fragment in one instruction (lane l: row l&15, word-group (l>>4)*4)
__device__ __forceinline__ void ldsm_x4(uint32_t* d, uint32_t saddr) {
    asm volatile("ldmatrix.sync.aligned.m8n8.x4.shared.b16 {%0,%1,%2,%3}, [%4];"
                 : "=r"(d[0]), "=r"(d[1]), "=r"(d[2]), "=r"(d[3])
                 : "r"(saddr));
}
__device__ __forceinline__ uint32_t f2tf(float x) {
    uint32_t r;
    asm("cvt.rna.tf32.f32 %0, %1;" : "=r"(r) : "f"(x));
    return r;
}
__device__ __forceinline__ void mma_tf32(float* c, const uint32_t* a, const uint32_t* b) {
    asm volatile(
        "mma.sync.aligned.m16n8k8.row.col.f32.tf32.tf32.f32 "
        "{%0,%1,%2,%3}, {%4,%5,%6,%7}, {%8,%9}, {%0,%1,%2,%3};"
        : "+f"(c[0]), "+f"(c[1]), "+f"(c[2]), "+f"(c[3])
        : "r"(a[0]), "r"(a[1]), "r"(a[2]), "r"(a[3]),
          "r"(b[0]), "r"(b[1]));
}

// ---------------------------------------------------------------------------
// tf32 pre-round passes
// ---------------------------------------------------------------------------
__device__ __forceinline__ float4 rnd4(float4 v) {
    v.x = __uint_as_float(f2tf(v.x));
    v.y = __uint_as_float(f2tf(v.y));
    v.z = __uint_as_float(f2tf(v.z));
    v.w = __uint_as_float(f2tf(v.w));
    return v;
}
__global__ void __launch_bounds__(256)
round_tf32_kernel(const float4* __restrict__ in, float4* __restrict__ out, int n4)
{
    const int i = blockIdx.x * blockDim.x + threadIdx.x;
    if (i < n4) out[i] = rnd4(in[i]);
}
__global__ void __launch_bounds__(256)
round2_tf32_kernel(const float4* __restrict__ a, float4* __restrict__ ao, int na4,
                   const float4* __restrict__ b, float4* __restrict__ bo, int nb4)
{
    const int i = blockIdx.x * blockDim.x + threadIdx.x;
    if (i < na4) ao[i] = rnd4(a[i]);
    else if (i < na4 + nb4) bo[i - na4] = rnd4(b[i - na4]);
}

// ---------------------------------------------------------------------------
// Fused batched tf32 GEMM, 3-stage cp.async, ldmatrix A frags, CVT-free.
// 128 threads, 2 CTAs/SM.
// MODE 0 (up):  z=0: H0 = rna(relu(xr@Wg1r+bg1)); z>=1: Hz = rna(relu(xr@W1r[z-1]+b1[z-1]))
//               grid (32, 64, 9)
// MODE 1 (down): P[z] = gate[:,z] * (H[z+1] @ W2r[z] + b2[z])
//               grid (8, 64, 8)
// ---------------------------------------------------------------------------
template<int MODE>
__global__ void __launch_bounds__(128, 2)
moe_fused(const float* __restrict__ Abase,
          const float* __restrict__ B0,
          const float* __restrict__ B1,
          const float* __restrict__ bias0,
          const float* __restrict__ bias1,
          const float* __restrict__ gate,
          float* __restrict__ Cbase)
{
    const int K = MODE ? EXP_DIM : IN_DIM;
    const int N = MODE ? IN_DIM : EXP_DIM;
    const int z = blockIdx.z;

    const float *A, *B, *bias;
    float* C;
    if (MODE == 0) {
        A    = Abase;
        B    = z ? B1 + (size_t)(z - 1) * IN_DIM * EXP_DIM : B0;
        bias = z ? bias1 + (size_t)(z - 1) * EXP_DIM : bias0;
        C    = Cbase + (size_t)z * N_TOKENS * EXP_DIM;
    } else {
        A    = Abase + (size_t)(z + 1) * N_TOKENS * EXP_DIM;
        B    = B0 + (size_t)z * EXP_DIM * IN_DIM;
        bias = bias0 + (size_t)z * IN_DIM;
        C    = Cbase + (size_t)z * N_TOKENS * IN_DIM;
    }

    extern __shared__ __align__(16) float smem[];
    const int tid    = threadIdx.x;
    const int lane   = tid & 31;
    const int wid    = tid >> 5;
    const int warp_m = wid >> 1;       // 0..1
    const int warp_n = wid & 1;        // 0..1
    const int wm0    = warp_m * 64;
    const int wn0    = warp_n * 64;
    const int m0     = blockIdx.y * BM;
    const int n0     = blockIdx.x * BN;
    const int r      = lane >> 2;      // 0..7
    const int q      = lane & 3;       // 0..3

    float acc[4][8][4];
    #pragma unroll
    for (int mi = 0; mi < 4; mi++)
        #pragma unroll
        for (int ni = 0; ni < 8; ni++)
            #pragma unroll
            for (int j = 0; j < 4; j++) acc[mi][ni][j] = 0.f;

    const uint32_t s_base = smem_u32(smem);
    const int KT = K >> 5;

    // cp.async fill (128 threads):
    // A tile 128x32: 8 chunks/row -> row = tid>>3 (+16*i, 8 iters), chunk = tid&7
    // B tile 32x128: 32 chunks/row -> row = tid>>5 (+4*i, 8 iters), chunk = tid&31
    const int a_id_row = tid >> 3, a_id_kq = tid & 7;
    const int b_id_row = tid >> 5, b_id_nq = tid & 31;

    auto load_tile = [&](int kt, int buf) {
        const int k0 = kt << 5;
        const uint32_t abase = s_base + (uint32_t)buf * BUF_WORDS * 4u;
        const uint32_t bbase = abase + (uint32_t)A_WORDS * 4u;
        #pragma unroll
        for (int i = 0; i < 8; i++) {
            const int row = a_id_row + (i << 4);
            cp16(abase + (uint32_t)(row * A_STRIDE + (a_id_kq << 2)) * 4u,
                 A + (size_t)(m0 + row) * K + k0 + (a_id_kq << 2));
        }
        #pragma unroll
        for (int i = 0; i < 8; i++) {
            const int row = b_id_row + (i << 2);
            cp16(bbase + (uint32_t)(row * B_STRIDE + (b_id_nq << 2)) * 4u,
                 B + (size_t)(k0 + row) * N + n0 + (b_id_nq << 2));
        }
    };

    load_tile(0, 0);
    cp_commit();
    if (KT > 1) { load_tile(1, 1); cp_commit(); }

    // ldmatrix per-lane source offset (row l&15, word-group (l>>4)*4)
    const uint32_t a_frag_off =
        (uint32_t)(((wm0 + (lane & 15)) * A_STRIDE + ((lane >> 4) << 2)) << 2);

    int cur = 0, pre = 2;

    for (int kt = 0; kt < KT; kt++) {
        if (kt + 1 < KT) cp_wait<1>(); else cp_wait<0>();
        __syncthreads();

        if (kt + 2 < KT) { load_tile(kt + 2, pre); cp_commit(); }

        const uint32_t a_frag = s_base + (uint32_t)cur * BUF_WORDS * 4u + a_frag_off;
        const uint32_t* __restrict__ Bq =
            reinterpret_cast<const uint32_t*>(smem + (size_t)cur * BUF_WORDS)
            + A_WORDS + q * B_STRIDE + wn0 + r;

        #pragma unroll
        for (int ks = 0; ks < 4; ks++) {
            const int kb = ks << 3;
            uint32_t af[4][4];
            #pragma unroll
            for (int mi = 0; mi < 4; mi++)
                ldsm_x4(af[mi], a_frag + (uint32_t)((((mi << 4) * A_STRIDE) + kb) << 2));
            uint32_t bf[8][2];
            const uint32_t* __restrict__ p = Bq + kb * B_STRIDE;
            #pragma unroll
            for (int ni = 0; ni < 8; ni++) {
                bf[ni][0] = p[ni << 3];
                bf[ni][1] = p[4 * B_STRIDE + (ni << 3)];
            }
            #pragma unroll
            for (int mi = 0; mi < 4; mi++)
                #pragma unroll
                for (int ni = 0; ni < 8; ni++)
                    mma_tf32(acc[mi][ni], af[mi], bf[ni]);
        }

        cur = (cur == N_STAGES - 1) ? 0 : cur + 1;
        pre = (pre == N_STAGES - 1) ? 0 : pre + 1;
    }

    // ---------------- Epilogue ----------------
    float gwv[4][2];
    if (MODE == 1) {
        #pragma unroll
        for (int mi = 0; mi < 4; mi++)
            #pragma unroll
            for (int h = 0; h < 2; h++) {
                const int m = m0 + wm0 + (mi << 4) + r + (h << 3);
                gwv[mi][h] = __ldg(gate + (size_t)m * N_EXPERTS + z);
            }
    }

    #pragma unroll
    for (int ni = 0; ni < 8; ni++) {
        const int n = n0 + wn0 + (ni << 3) + (q << 1);
        const float b0 = __ldg(bias + n);
        const float b1v = __ldg(bias + n + 1);
        #pragma unroll
        for (int mi = 0; mi < 4; mi++) {
            #pragma unroll
            for (int h = 0; h < 2; h++) {
                const int m = m0 + wm0 + (mi << 4) + r + (h << 3);
                float v0 = acc[mi][ni][2 * h]     + b0;
                float v1 = acc[mi][ni][2 * h + 1] + b1v;
                float2* p = reinterpret_cast<float2*>(C + (size_t)m * N + n);
                if (MODE == 0) {
                    v0 = __uint_as_float(f2tf(fmaxf(v0, 0.f)));
                    v1 = __uint_as_float(f2tf(fmaxf(v1, 0.f)));
                } else {
                    v0 *= gwv[mi][h];
                    v1 *= gwv[mi][h];
                }
                *p = make_float2(v0, v1);
            }
        }
    }
}

// ---------------------------------------------------------------------------
// out = sum_e P[e]  (float4, deterministic fp32 order)
// ---------------------------------------------------------------------------
__global__ void __launch_bounds__(256)
reduce8_kernel(const float4* __restrict__ P, float4* __restrict__ out, int n4)
{
    const int i = blockIdx.x * blockDim.x + threadIdx.x;
    if (i < n4) {
        float4 s = P[i];
        #pragma unroll
        for (int e = 1; e < N_EXPERTS; e++) {
            const float4 t = P[(size_t)e * n4 + i];
            s.x += t.x; s.y += t.y; s.z += t.z; s.w += t.w;
        }
        out[i] = s;
    }
}

// ---------------------------------------------------------------------------
// Gate logits + softmax: one warp per token.
// ---------------------------------------------------------------------------
__global__ void __launch_bounds__(256)
gate_softmax_kernel(const float* __restrict__ G,
                    const float* __restrict__ Wg2,
                    const float* __restrict__ bg2,
                    float* __restrict__ gate)
{
    const int token = (blockIdx.x * blockDim.x + threadIdx.x) >> 5;
    const int lane = threadIdx.x & 31;
    const float* g = G + (size_t)token * EXP_DIM;

    float acc[8];
    #pragma unroll
    for (int e = 0; e < 8; e++) acc[e] = 0.f;

    for (int h = lane; h < EXP_DIM; h += 32) {
        const float gv = g[h];
        const float4* w = reinterpret_cast<const float4*>(Wg2 + (size_t)h * 8);
        const float4 wa = w[0];
        const float4 wb = w[1];
        acc[0] = fmaf(gv, wa.x, acc[0]);
        acc[1] = fmaf(gv, wa.y, acc[1]);
        acc[2] = fmaf(gv, wa.z, acc[2]);
        acc[3] = fmaf(gv, wa.w, acc[3]);
        acc[4] = fmaf(gv, wb.x, acc[4]);
        acc[5] = fmaf(gv, wb.y, acc[5]);
        acc[6] = fmaf(gv, wb.z, acc[6]);
        acc[7] = fmaf(gv, wb.w, acc[7]);
    }
    #pragma unroll
    for (int o = 16; o > 0; o >>= 1) {
        #pragma unroll
        for (int e = 0; e < 8; e++)
            acc[e] += __shfl_xor_sync(0xffffffff, acc[e], o);
    }
    if (lane == 0) {
        float l[8], p[8];
        float m = -1e30f;
        #pragma unroll
        for (int e = 0; e < 8; e++) { l[e] = acc[e] + bg2[e]; m = fmaxf(m, l[e]); }
        float s = 0.f;
        #pragma unroll
        for (int e = 0; e < 8; e++) { p[e] = expf(l[e] - m); s += p[e]; }
        const float inv = 1.f / s;
        #pragma unroll
        for (int e = 0; e < 8; e++) gate[(size_t)token * 8 + e] = p[e] * inv;
    }
}

// ---------------------------------------------------------------------------
// 7 launches: round2(x,Wg1) -> round(W1) -> round(W2) -> fused up (z=0..8)
// -> softmax -> fused down (z=0..7, partials) -> reduce.
// ---------------------------------------------------------------------------
extern "C" void kernel_launch(void* const* d_in, const int* in_sizes, int n_in,
                              void* d_out, int out_size) {
    (void)in_sizes; (void)n_in; (void)out_size;
    const float* x   = (const float*)d_in[0];
    const float* Wg1 = (const float*)d_in[1];
    const float* bg1 = (const float*)d_in[2];
    const float* Wg2 = (const float*)d_in[3];
    const float* bg2 = (const float*)d_in[4];
    const float* W1  = (const float*)d_in[5];
    const float* b1  = (const float*)d_in[6];
    const float* W2  = (const float*)d_in[7];
    const float* b2  = (const float*)d_in[8];
    float* out = (float*)d_out;

    float *H, *P, *gate, *xr, *Wg1r, *W1r, *W2r;
    cudaGetSymbolAddress((void**)&H,    g_H);
    cudaGetSymbolAddress((void**)&P,    g_P);
    cudaGetSymbolAddress((void**)&gate, g_gate);
    cudaGetSymbolAddress((void**)&xr,   g_xr);
    cudaGetSymbolAddress((void**)&Wg1r, g_Wg1r);
    cudaGetSymbolAddress((void**)&W1r,  g_W1r);
    cudaGetSymbolAddress((void**)&W2r,  g_W2r);

    cudaFuncSetAttribute(moe_fused<0>, cudaFuncAttributeMaxDynamicSharedMemorySize,
                         SMEM_BYTES);
    cudaFuncSetAttribute(moe_fused<1>, cudaFuncAttributeMaxDynamicSharedMemorySize,
                         SMEM_BYTES);

    // 1: round x + Wg1
    {
        const int na4 = (N_TOKENS * IN_DIM) / 4;
        const int nb4 = (IN_DIM * EXP_DIM) / 4;
        round2_tf32_kernel<<<(na4 + nb4 + 255) / 256, 256>>>(
            (const float4*)x, (float4*)xr, na4,
            (const float4*)Wg1, (float4*)Wg1r, nb4);
    }
    // 2: round W1, 3: round W2
    {
        const int n4 = (int)(((size_t)N_EXPERTS * IN_DIM * EXP_DIM) >> 2);
        round_tf32_kernel<<<(n4 + 255) / 256, 256>>>(
            (const float4*)W1, (float4*)W1r, n4);
        round_tf32_kernel<<<(n4 + 255) / 256, 256>>>(
            (const float4*)W2, (float4*)W2r, n4);
    }

    const dim3 blk(128);

    // 4: fused up-GEMMs (gate hidden + 8 experts)
    moe_fused<0><<<dim3(EXP_DIM / BN, N_TOKENS / BM, N_EXPERTS + 1), blk, SMEM_BYTES>>>(
        xr, Wg1r, W1r, bg1, b1, nullptr, H);

    // 5: gate softmax (reads H z=0)
    gate_softmax_kernel<<<N_TOKENS / 8, 256>>>(H, Wg2, bg2, gate);

    // 6: fused down-GEMMs -> per-expert partials
    moe_fused<1><<<dim3(IN_DIM / BN, N_TOKENS / BM, N_EXPERTS), blk, SMEM_BYTES>>>(
        H, W2r, nullptr, b2, nullptr, gate, P);

    // 7: reduce partials -> out
    {
        const int n4 = (N_TOKENS * IN_DIM) / 4;
        reduce8_kernel<<<(n4 + 255) / 256, 256>>>((const float4*)P, (float4*)out, n4);
    }
}